// round 14
// baseline (speedup 1.0000x reference)
#include <cuda_runtime.h>
#include <math.h>

#define A_N   20480
#define G_N   5
#define P_N   (A_N * G_N)           // 102400 pairs
#define NVOX  (128 * 128 * 128)
#define WIN   10                    // gaussian window width (slots 0..9), centered: margins in [4,5]
#define MAXE  (P_N * 8)
#define CHUNK 128
#define NB    64                    // batch size == 2 warps' ballot width (ull masks)
#define MAXC  (512 + MAXE / CHUNK)  // max chunk descriptors (6912)
#define PRE_BLOCKS ((P_N + 255) / 256)          // 400
#define ZERO_BLOCKS (NVOX / 4 / 256)            // 2048
#define RED_BLOCKS 512

typedef unsigned long long ull;

// ---------------- device scratch (d_counts/d_donecnt invariants restored each run) ----------------
__device__ float        d_gx[P_N * 16];
__device__ float        d_gy[P_N * 16];
__device__ float        d_gz[P_N * 16];     // prefactor folded in
__device__ int4         d_meta[P_N];        // ix0, iy0, iz0, packed tile spans (w=-1: none)
__device__ float        d_vol[NVOX];
__device__ unsigned int d_counts[512];
__device__ unsigned int d_segstart[512];
__device__ unsigned int d_cursor[512];
__device__ uint2        d_chunkdesc[MAXC];  // {entry start, tile | (len<<16)}
__device__ unsigned int d_nchunks;
__device__ unsigned int d_entries[MAXE];    // (tile << 17) | pair
__device__ unsigned int d_total;
__device__ unsigned int d_donecnt;
__device__ double       d_sums[3];          // S1, S2, S3

// ---------------- f32x2 helpers ----------------
__device__ __forceinline__ ull pack2(float lo, float hi) {
    ull r; asm("mov.b64 %0, {%1, %2};" : "=l"(r) : "f"(lo), "f"(hi)); return r;
}
__device__ __forceinline__ void unpack2(ull v, float& lo, float& hi) {
    asm("mov.b64 {%0, %1}, %2;" : "=f"(lo), "=f"(hi) : "l"(v));
}
__device__ __forceinline__ ull fma2(ull a, ull b, ull c) {
    ull d; asm("fma.rn.f32x2 %0, %1, %2, %3;" : "=l"(d) : "l"(a), "l"(b), "l"(c)); return d;
}
__device__ __forceinline__ void red2(float* p, ull v) {
    float lo, hi; unpack2(v, lo, hi);
    asm volatile("red.global.add.v2.f32 [%0], {%1, %2};" :: "l"(p), "f"(lo), "f"(hi) : "memory");
}

// ---------------- K2: rotate + 1D gaussians + tile counting, fused d_vol zeroing ----------------
__global__ void k_precompute(const float* __restrict__ quat,
                             const float* __restrict__ offset,
                             const float* __restrict__ pos,
                             const float* __restrict__ amp,
                             const float* __restrict__ var) {
    int t = threadIdx.x;

    if (blockIdx.x >= PRE_BLOCKS) {
        int i = (blockIdx.x - PRE_BLOCKS) * 256 + t;
        ((float4*)d_vol)[i] = make_float4(0.f, 0.f, 0.f, 0.f);
        return;
    }

    __shared__ unsigned int scount[512];
    scount[t] = 0u; scount[t + 256] = 0u;
    __syncthreads();

    int p = blockIdx.x * 256 + t;
    int w = -1;
    if (p < P_N) {
        float qw = quat[0], qx = quat[1], qy = quat[2], qz = quat[3];
        float qn = rsqrtf(qw * qw + qx * qx + qy * qy + qz * qz);
        qw *= qn; qx *= qn; qy *= qn; qz *= qn;
        float R00 = 1.f - 2.f * (qy * qy + qz * qz);
        float R01 = 2.f * (qx * qy - qw * qz);
        float R02 = 2.f * (qx * qz + qw * qy);
        float R10 = 2.f * (qx * qy + qw * qz);
        float R11 = 1.f - 2.f * (qx * qx + qz * qz);
        float R12 = 2.f * (qy * qz - qw * qx);
        float R20 = 2.f * (qx * qz - qw * qy);
        float R21 = 2.f * (qy * qz + qw * qx);
        float R22 = 1.f - 2.f * (qx * qx + qy * qy);

        int a = p / G_N;
        float px = pos[a * 3 + 0], py = pos[a * 3 + 1], pz = pos[a * 3 + 2];
        float cx = px * R00 + py * R10 + pz * R20 + offset[0];
        float cy = px * R01 + py * R11 + pz * R21 + offset[1];
        float cz = px * R02 + py * R12 + pz * R22 + offset[2];

        float v    = var[p];
        float am   = amp[p];
        float r    = rsqrtf(6.283185307179586f * v);
        float pref = am * r * r * r;            // amp * (2*pi*var)^(-3/2)
        float ninv = -0.5f / v;

        // even-aligned, centered window [ix0 .. ix0+9]; margins in [4,5] both sides
        int ix0 = ((int)floorf(cx) + 60) & ~1;
        int iy0 = ((int)floorf(cy) + 60) & ~1;
        int iz0 = ((int)floorf(cz) + 60) & ~1;

        float q2 = __expf(2.f * ninv);
        float g[16];
        {
            float d0 = (float)(ix0 - 64) - cx;
            float e  = __expf(ninv * d0 * d0);
            float rr = __expf(ninv * (2.f * d0 + 1.f));
            #pragma unroll
            for (int i = 0; i < 16; i++) { g[i] = (i < WIN) ? e : 0.f; e *= rr; rr *= q2; }
            float4* dst = (float4*)&d_gx[p * 16];
            dst[0] = make_float4(g[0], g[1], g[2], g[3]);
            dst[1] = make_float4(g[4], g[5], g[6], g[7]);
            dst[2] = make_float4(g[8], g[9], 0.f, 0.f);
            dst[3] = make_float4(0.f, 0.f, 0.f, 0.f);
        }
        {
            float d0 = (float)(iy0 - 64) - cy;
            float e  = __expf(ninv * d0 * d0);
            float rr = __expf(ninv * (2.f * d0 + 1.f));
            #pragma unroll
            for (int i = 0; i < 16; i++) { g[i] = (i < WIN) ? e : 0.f; e *= rr; rr *= q2; }
            float4* dst = (float4*)&d_gy[p * 16];
            dst[0] = make_float4(g[0], g[1], g[2], g[3]);
            dst[1] = make_float4(g[4], g[5], g[6], g[7]);
            dst[2] = make_float4(g[8], g[9], 0.f, 0.f);
            dst[3] = make_float4(0.f, 0.f, 0.f, 0.f);
        }
        {
            float d0 = (float)(iz0 - 64) - cz;
            float e  = pref * __expf(ninv * d0 * d0);
            float rr = __expf(ninv * (2.f * d0 + 1.f));
            #pragma unroll
            for (int i = 0; i < 16; i++) { g[i] = (i < WIN) ? e : 0.f; e *= rr; rr *= q2; }
            float4* dst = (float4*)&d_gz[p * 16];
            dst[0] = make_float4(g[0], g[1], g[2], g[3]);
            dst[1] = make_float4(g[4], g[5], g[6], g[7]);
            dst[2] = make_float4(g[8], g[9], 0.f, 0.f);
            dst[3] = make_float4(0.f, 0.f, 0.f, 0.f);
        }

        int xlo = max(ix0, 0), xhi = min(ix0 + WIN - 1, 127);
        int ylo = max(iy0, 0), yhi = min(iy0 + WIN - 1, 127);
        int zlo = max(iz0, 0), zhi = min(iz0 + WIN - 1, 127);
        if (xlo <= xhi && ylo <= yhi && zlo <= zhi) {
            int txlo = xlo >> 4, txhi = xhi >> 4;
            int tylo = ylo >> 4, tyhi = yhi >> 4;
            int tzlo = zlo >> 4, tzhi = zhi >> 4;
            w = txlo | (txhi << 3) | (tylo << 6) | (tyhi << 9) | (tzlo << 12) | (tzhi << 15);
            for (int tz = tzlo; tz <= tzhi; tz++)
                for (int ty = tylo; ty <= tyhi; ty++)
                    for (int tx = txlo; tx <= txhi; tx++)
                        atomicAdd(&scount[(tz << 6) | (ty << 3) | tx], 1u);
        }
        d_meta[p] = make_int4(ix0, iy0, iz0, w);
    }
    __syncthreads();
    for (int i = t; i < 512; i += 256) {
        unsigned int c = scount[i];
        if (c) atomicAdd(&d_counts[i], c);   // d_counts pre-zeroed by previous run's epilogue
    }
}

// ---------------- K3: scans + chunk descriptor emission + sums zero ----------------
__global__ void k_scan() {
    __shared__ unsigned int s[512];
    int t = threadIdx.x;
    unsigned int own = d_counts[t];
    s[t] = own;
    __syncthreads();
    for (int off = 1; off < 512; off <<= 1) {
        unsigned int v = (t >= off) ? s[t - off] : 0u;
        __syncthreads();
        s[t] += v;
        __syncthreads();
    }
    unsigned int segstart = s[t] - own;
    d_segstart[t] = segstart;
    d_cursor[t]   = segstart;
    if (t == 511) d_total = s[511];
    if (t < 3)    d_sums[t] = 0.0;
    __syncthreads();

    unsigned int nch = (own + CHUNK - 1) / CHUNK;
    s[t] = nch;
    __syncthreads();
    for (int off = 1; off < 512; off <<= 1) {
        unsigned int v = (t >= off) ? s[t - off] : 0u;
        __syncthreads();
        s[t] += v;
        __syncthreads();
    }
    unsigned int cb = s[t] - nch;
    if (t == 511) d_nchunks = s[511];

    for (unsigned int j = 0; j * CHUNK < own; j++) {
        unsigned int len = min((unsigned int)CHUNK, own - j * CHUNK);
        d_chunkdesc[cb + j] = make_uint2(segstart + j * CHUNK,
                                         (unsigned int)t | (len << 16));
    }
}

// ---------------- K4: fill entry list, block-aggregated cursors ----------------
__global__ void k_fill() {
    __shared__ unsigned int scount[512];
    __shared__ unsigned int sbase[512];
    int t = threadIdx.x;
    scount[t] = 0u; scount[t + 256] = 0u;
    __syncthreads();

    int p = blockIdx.x * 256 + t;
    int w = (p < P_N) ? d_meta[p].w : -1;
    int txlo = 0, txhi = -1, tylo = 0, tyhi = -1, tzlo = 0, tzhi = -1;
    if (w >= 0) {
        txlo =  w        & 7; txhi = (w >> 3)  & 7;
        tylo = (w >> 6)  & 7; tyhi = (w >> 9)  & 7;
        tzlo = (w >> 12) & 7; tzhi = (w >> 15) & 7;
        for (int tz = tzlo; tz <= tzhi; tz++)
            for (int ty = tylo; ty <= tyhi; ty++)
                for (int tx = txlo; tx <= txhi; tx++)
                    atomicAdd(&scount[(tz << 6) | (ty << 3) | tx], 1u);
    }
    __syncthreads();
    for (int i = t; i < 512; i += 256) {
        unsigned int c = scount[i];
        sbase[i] = c ? atomicAdd(&d_cursor[i], c) : 0u;
    }
    __syncthreads();
    if (w >= 0) {
        for (int tz = tzlo; tz <= tzhi; tz++)
            for (int ty = tylo; ty <= tyhi; ty++)
                for (int tx = txlo; tx <= txhi; tx++) {
                    int tile = (tz << 6) | (ty << 3) | tx;
                    unsigned int posn = atomicAdd(&sbase[tile], 1u);
                    d_entries[posn] = ((unsigned int)tile << 17) | (unsigned int)p;
                }
    }
}

// ---------------- K5: splat — one chunk per CTA, 64-entry batches, dual-entry k-loop ----------------
__global__ void __launch_bounds__(128) k_splat() {
    __shared__ __align__(16) float sgx[2][NB][16];
    __shared__ __align__(16) float sgy[2][NB][16];
    __shared__ __align__(16) float sgz[2][NB][16];
    __shared__ unsigned int szmask[2][NB];

    if (blockIdx.x >= d_nchunks) return;
    uint2 desc = d_chunkdesc[blockIdx.x];
    unsigned int s   = desc.x;
    int tile         = (int)(desc.y & 0x1FFu);
    unsigned int len = desc.y >> 16;
    unsigned int e_end = s + len;

    int X0 =  (tile       & 7) << 4;
    int Y0 = ((tile >> 3) & 7) << 4;
    int Z0 = ((tile >> 6) & 7) << 4;

    int t    = threadIdx.x;
    int y    = t & 15;        // owned y row
    int zp   = t >> 4;        // owned z rows: 2*zp, 2*zp+1
    int wid  = t >> 5;        // warp id 0..3, covers z in [4w, 4w+4)
    int lane = t & 31;

    ull acc[2][8];            // [zz][x-pair]
    #pragma unroll
    for (int r = 0; r < 2; r++)
        #pragma unroll
        for (int i = 0; i < 8; i++) acc[r][i] = 0ull;

    // stage: float2 granularity (slots pair up: offsets and 2*l2 both even)
    auto stage = [&](int buf, unsigned int base, int n) {
        #pragma unroll
        for (int s2 = t; s2 < NB * 8; s2 += 128) {
            int b = s2 >> 3, l2 = s2 & 7;
            if (b < n) {
                unsigned int ent = d_entries[base + (unsigned int)b];
                int pid = (int)(ent & 0x1FFFFu);
                int4 mt = d_meta[pid];
                int ox = X0 - mt.x, oy = Y0 - mt.y, oz = Z0 - mt.z;
                int ix = 2 * l2 + ox, iy = 2 * l2 + oy, iz = 2 * l2 + oz;
                float2 vx = make_float2(0.f, 0.f), vy = vx, vz = vx;
                if ((unsigned)ix < (unsigned)WIN) vx = *(const float2*)&d_gx[pid * 16 + ix];
                if ((unsigned)iy < (unsigned)WIN) vy = *(const float2*)&d_gy[pid * 16 + iy];
                if ((unsigned)iz < (unsigned)WIN) vz = *(const float2*)&d_gz[pid * 16 + iz];
                *(float2*)&sgx[buf][b][2 * l2] = vx;
                *(float2*)&sgy[buf][b][2 * l2] = vy;
                *(float2*)&sgz[buf][b][2 * l2] = vz;
                if (l2 == 0) {
                    int loz = max(0, -oz), hiz = min(15, (WIN - 1) - oz);
                    unsigned int c = 0u;
                    #pragma unroll
                    for (int w2 = 0; w2 < 4; w2++)
                        if (loz <= 4 * w2 + 3 && hiz >= 4 * w2) c |= 1u << w2;
                    szmask[buf][b] = c;
                }
            } else if (l2 == 0) {
                szmask[buf][b] = 0u;
            }
        }
    };

    int nbatch = (int)((len + NB - 1) / NB);
    stage(0, s, (int)min((unsigned int)NB, len));

    for (int i = 0; i < nbatch; i++) {
        __syncthreads();
        int cur = i & 1;
        if (i + 1 < nbatch) {
            unsigned int bnext = s + (unsigned int)(i + 1) * NB;
            stage(cur ^ 1, bnext, (int)min((unsigned int)NB, e_end - bnext));
        }

        // 64-entry pass mask for this warp's z band
        unsigned int emA = szmask[cur][lane];
        unsigned int emB = szmask[cur][lane + 32];
        unsigned int mlo = __ballot_sync(0xFFFFFFFFu, (emA >> wid) & 1u);
        unsigned int mhi = __ballot_sync(0xFFFFFFFFu, (emB >> wid) & 1u);
        ull m = ((ull)mhi << 32) | (ull)mlo;

        while (m) {
            int k1 = __ffsll(m) - 1;
            m &= m - 1;
            float sec = m ? 1.f : 0.f;           // second entry valid?
            int k2 = m ? (__ffsll(m) - 1) : k1;  // duplicate k1, zeroed by sec
            m &= m - 1;                          // safe at m==0

            float  gy1 = sgy[cur][k1][y];
            float2 gza = *(const float2*)&sgz[cur][k1][2 * zp];
            float  gy2 = sgy[cur][k2][y] * sec;
            float2 gzb = *(const float2*)&sgz[cur][k2][2 * zp];
            float a0 = gy1 * gza.x, a1 = gy1 * gza.y;
            float b0 = gy2 * gzb.x, b1 = gy2 * gzb.y;
            ull ca0 = pack2(a0, a0), ca1 = pack2(a1, a1);
            ull cb0 = pack2(b0, b0), cb1 = pack2(b1, b1);

            ulonglong2 pa = *(const ulonglong2*)&sgx[cur][k1][0];
            ulonglong2 pb = *(const ulonglong2*)&sgx[cur][k1][4];
            ulonglong2 pc = *(const ulonglong2*)&sgx[cur][k1][8];
            ulonglong2 pd = *(const ulonglong2*)&sgx[cur][k1][12];
            ulonglong2 qa = *(const ulonglong2*)&sgx[cur][k2][0];
            ulonglong2 qb = *(const ulonglong2*)&sgx[cur][k2][4];
            ulonglong2 qc = *(const ulonglong2*)&sgx[cur][k2][8];
            ulonglong2 qd = *(const ulonglong2*)&sgx[cur][k2][12];

            acc[0][0] = fma2(ca0, pa.x, acc[0][0]); acc[0][1] = fma2(ca0, pa.y, acc[0][1]);
            acc[0][2] = fma2(ca0, pb.x, acc[0][2]); acc[0][3] = fma2(ca0, pb.y, acc[0][3]);
            acc[0][4] = fma2(ca0, pc.x, acc[0][4]); acc[0][5] = fma2(ca0, pc.y, acc[0][5]);
            acc[0][6] = fma2(ca0, pd.x, acc[0][6]); acc[0][7] = fma2(ca0, pd.y, acc[0][7]);
            acc[1][0] = fma2(ca1, pa.x, acc[1][0]); acc[1][1] = fma2(ca1, pa.y, acc[1][1]);
            acc[1][2] = fma2(ca1, pb.x, acc[1][2]); acc[1][3] = fma2(ca1, pb.y, acc[1][3]);
            acc[1][4] = fma2(ca1, pc.x, acc[1][4]); acc[1][5] = fma2(ca1, pc.y, acc[1][5]);
            acc[1][6] = fma2(ca1, pd.x, acc[1][6]); acc[1][7] = fma2(ca1, pd.y, acc[1][7]);

            acc[0][0] = fma2(cb0, qa.x, acc[0][0]); acc[0][1] = fma2(cb0, qa.y, acc[0][1]);
            acc[0][2] = fma2(cb0, qb.x, acc[0][2]); acc[0][3] = fma2(cb0, qb.y, acc[0][3]);
            acc[0][4] = fma2(cb0, qc.x, acc[0][4]); acc[0][5] = fma2(cb0, qc.y, acc[0][5]);
            acc[0][6] = fma2(cb0, qd.x, acc[0][6]); acc[0][7] = fma2(cb0, qd.y, acc[0][7]);
            acc[1][0] = fma2(cb1, qa.x, acc[1][0]); acc[1][1] = fma2(cb1, qa.y, acc[1][1]);
            acc[1][2] = fma2(cb1, qb.x, acc[1][2]); acc[1][3] = fma2(cb1, qb.y, acc[1][3]);
            acc[1][4] = fma2(cb1, qc.x, acc[1][4]); acc[1][5] = fma2(cb1, qc.y, acc[1][5]);
            acc[1][6] = fma2(cb1, qd.x, acc[1][6]); acc[1][7] = fma2(cb1, qd.y, acc[1][7]);
        }
    }

    #pragma unroll
    for (int zz = 0; zz < 2; zz++) {
        int rb = ((Z0 + 2 * zp + zz) * 128 + (Y0 + y)) * 128 + X0;
        #pragma unroll
        for (int i2 = 0; i2 < 8; i2++)
            if (acc[zz][i2]) red2(&d_vol[rb + 2 * i2], acc[zz][i2]);
    }
}

// ---------------- K6: fused triple reduction + final (last-block epilogue) ----------------
__global__ void k_reduce(const float* __restrict__ grid, float* __restrict__ out) {
    __shared__ double sh0[256], sh1[256], sh2[256];
    int t = threadIdx.x;
    float s1 = 0.f, s2 = 0.f, s3 = 0.f;
    for (int i = blockIdx.x * 256 + t; i < NVOX; i += gridDim.x * 256) {
        float v = d_vol[i];
        float g = grid[i];
        s1 += v * g;
        s2 += v * v;
        s3 += g * g;
    }
    sh0[t] = (double)s1; sh1[t] = (double)s2; sh2[t] = (double)s3;
    __syncthreads();
    for (int off = 128; off > 0; off >>= 1) {
        if (t < off) {
            sh0[t] += sh0[t + off];
            sh1[t] += sh1[t + off];
            sh2[t] += sh2[t + off];
        }
        __syncthreads();
    }
    if (t == 0) {
        atomicAdd(&d_sums[0], sh0[0]);
        atomicAdd(&d_sums[1], sh1[0]);
        atomicAdd(&d_sums[2], sh2[0]);
        __threadfence();
        unsigned int done = atomicAdd(&d_donecnt, 1u);
        if (done == gridDim.x - 1) {
            // last block: finish scalar + restore invariants for next run
            d_donecnt = 0u;
            out[0] = (float)(1.0 - d_sums[0] / sqrt(d_sums[1] * d_sums[2]));
            for (int i = 0; i < 512; i++) d_counts[i] = 0u;
        }
    }
}

extern "C" void kernel_launch(void* const* d_in, const int* in_sizes, int n_in,
                              void* d_out, int out_size) {
    const float* quat   = (const float*)d_in[0];
    const float* offset = (const float*)d_in[1];
    const float* pos    = (const float*)d_in[2];
    const float* amp    = (const float*)d_in[3];
    const float* var    = (const float*)d_in[4];
    const float* grid   = (const float*)d_in[5];
    float* out = (float*)d_out;

    k_precompute<<<PRE_BLOCKS + ZERO_BLOCKS, 256>>>(quat, offset, pos, amp, var);
    k_scan<<<1, 512>>>();
    k_fill<<<(P_N + 255) / 256, 256>>>();
    k_splat<<<MAXC, 128>>>();
    k_reduce<<<RED_BLOCKS, 256>>>(grid, out);
}

// round 16
// speedup vs baseline: 1.1081x; 1.1081x over previous
#include <cuda_runtime.h>
#include <math.h>

#define A_N   20480
#define G_N   5
#define P_N   (A_N * G_N)           // 102400 pairs
#define NVOX  (128 * 128 * 128)
#define WIN   10                    // gaussian window width (slots 0..9), centered: margins in [4,5]
#define MAXE  (P_N * 8)
#define CHUNK 128
#define NB    32                    // batch size == warp width (ballot compaction)
#define MAXC  (512 + MAXE / CHUNK)  // max chunk descriptors (6912)
#define PRE_BLOCKS ((P_N + 255) / 256)          // 400
#define ZERO_BLOCKS (NVOX / 4 / 256)            // 2048

typedef unsigned long long ull;

// ---------------- device scratch (d_counts invariant: zeroed at end of every run) ----------------
__device__ float        d_gx[P_N * 16];
__device__ float        d_gy[P_N * 16];
__device__ float        d_gz[P_N * 16];     // prefactor folded in
__device__ int4         d_meta[P_N];        // ix0, iy0, iz0, packed tile spans (w=-1: none)
__device__ float        d_vol[NVOX];
__device__ unsigned int d_counts[512];
__device__ unsigned int d_segstart[512];
__device__ unsigned int d_cursor[512];
__device__ uint2        d_chunkdesc[MAXC];  // {entry start, tile | (len<<16)}
__device__ unsigned int d_nchunks;
__device__ unsigned int d_entries[MAXE];    // (tile << 17) | pair
__device__ unsigned int d_total;
__device__ double       d_sums[3];          // S1, S2, S3

// ---------------- f32x2 helpers ----------------
__device__ __forceinline__ ull pack2(float lo, float hi) {
    ull r; asm("mov.b64 %0, {%1, %2};" : "=l"(r) : "f"(lo), "f"(hi)); return r;
}
__device__ __forceinline__ void unpack2(ull v, float& lo, float& hi) {
    asm("mov.b64 {%0, %1}, %2;" : "=f"(lo), "=f"(hi) : "l"(v));
}
__device__ __forceinline__ ull fma2(ull a, ull b, ull c) {
    ull d; asm("fma.rn.f32x2 %0, %1, %2, %3;" : "=l"(d) : "l"(a), "l"(b), "l"(c)); return d;
}
__device__ __forceinline__ void red2(float* p, ull v) {
    float lo, hi; unpack2(v, lo, hi);
    asm volatile("red.global.add.v2.f32 [%0], {%1, %2};" :: "l"(p), "f"(lo), "f"(hi) : "memory");
}

// ---------------- K2: rotate + 1D gaussians + tile counting, fused d_vol zeroing ----------------
__global__ void k_precompute(const float* __restrict__ quat,
                             const float* __restrict__ offset,
                             const float* __restrict__ pos,
                             const float* __restrict__ amp,
                             const float* __restrict__ var) {
    int t = threadIdx.x;

    if (blockIdx.x >= PRE_BLOCKS) {
        int i = (blockIdx.x - PRE_BLOCKS) * 256 + t;
        ((float4*)d_vol)[i] = make_float4(0.f, 0.f, 0.f, 0.f);
        return;
    }

    __shared__ unsigned int scount[512];
    scount[t] = 0u; scount[t + 256] = 0u;
    __syncthreads();

    int p = blockIdx.x * 256 + t;
    int w = -1;
    if (p < P_N) {
        float qw = quat[0], qx = quat[1], qy = quat[2], qz = quat[3];
        float qn = rsqrtf(qw * qw + qx * qx + qy * qy + qz * qz);
        qw *= qn; qx *= qn; qy *= qn; qz *= qn;
        float R00 = 1.f - 2.f * (qy * qy + qz * qz);
        float R01 = 2.f * (qx * qy - qw * qz);
        float R02 = 2.f * (qx * qz + qw * qy);
        float R10 = 2.f * (qx * qy + qw * qz);
        float R11 = 1.f - 2.f * (qx * qx + qz * qz);
        float R12 = 2.f * (qy * qz - qw * qx);
        float R20 = 2.f * (qx * qz - qw * qy);
        float R21 = 2.f * (qy * qz + qw * qx);
        float R22 = 1.f - 2.f * (qx * qx + qy * qy);

        int a = p / G_N;
        float px = pos[a * 3 + 0], py = pos[a * 3 + 1], pz = pos[a * 3 + 2];
        float cx = px * R00 + py * R10 + pz * R20 + offset[0];
        float cy = px * R01 + py * R11 + pz * R21 + offset[1];
        float cz = px * R02 + py * R12 + pz * R22 + offset[2];

        float v    = var[p];
        float am   = amp[p];
        float r    = rsqrtf(6.283185307179586f * v);
        float pref = am * r * r * r;            // amp * (2*pi*var)^(-3/2)
        float ninv = -0.5f / v;

        // even-aligned, centered window [ix0 .. ix0+9]; margins in [4,5] both sides
        int ix0 = ((int)floorf(cx) + 60) & ~1;
        int iy0 = ((int)floorf(cy) + 60) & ~1;
        int iz0 = ((int)floorf(cz) + 60) & ~1;

        float q2 = __expf(2.f * ninv);
        float g[16];
        {
            float d0 = (float)(ix0 - 64) - cx;
            float e  = __expf(ninv * d0 * d0);
            float rr = __expf(ninv * (2.f * d0 + 1.f));
            #pragma unroll
            for (int i = 0; i < 16; i++) { g[i] = (i < WIN) ? e : 0.f; e *= rr; rr *= q2; }
            float4* dst = (float4*)&d_gx[p * 16];
            dst[0] = make_float4(g[0], g[1], g[2], g[3]);
            dst[1] = make_float4(g[4], g[5], g[6], g[7]);
            dst[2] = make_float4(g[8], g[9], 0.f, 0.f);
            dst[3] = make_float4(0.f, 0.f, 0.f, 0.f);
        }
        {
            float d0 = (float)(iy0 - 64) - cy;
            float e  = __expf(ninv * d0 * d0);
            float rr = __expf(ninv * (2.f * d0 + 1.f));
            #pragma unroll
            for (int i = 0; i < 16; i++) { g[i] = (i < WIN) ? e : 0.f; e *= rr; rr *= q2; }
            float4* dst = (float4*)&d_gy[p * 16];
            dst[0] = make_float4(g[0], g[1], g[2], g[3]);
            dst[1] = make_float4(g[4], g[5], g[6], g[7]);
            dst[2] = make_float4(g[8], g[9], 0.f, 0.f);
            dst[3] = make_float4(0.f, 0.f, 0.f, 0.f);
        }
        {
            float d0 = (float)(iz0 - 64) - cz;
            float e  = pref * __expf(ninv * d0 * d0);
            float rr = __expf(ninv * (2.f * d0 + 1.f));
            #pragma unroll
            for (int i = 0; i < 16; i++) { g[i] = (i < WIN) ? e : 0.f; e *= rr; rr *= q2; }
            float4* dst = (float4*)&d_gz[p * 16];
            dst[0] = make_float4(g[0], g[1], g[2], g[3]);
            dst[1] = make_float4(g[4], g[5], g[6], g[7]);
            dst[2] = make_float4(g[8], g[9], 0.f, 0.f);
            dst[3] = make_float4(0.f, 0.f, 0.f, 0.f);
        }

        int xlo = max(ix0, 0), xhi = min(ix0 + WIN - 1, 127);
        int ylo = max(iy0, 0), yhi = min(iy0 + WIN - 1, 127);
        int zlo = max(iz0, 0), zhi = min(iz0 + WIN - 1, 127);
        if (xlo <= xhi && ylo <= yhi && zlo <= zhi) {
            int txlo = xlo >> 4, txhi = xhi >> 4;
            int tylo = ylo >> 4, tyhi = yhi >> 4;
            int tzlo = zlo >> 4, tzhi = zhi >> 4;
            w = txlo | (txhi << 3) | (tylo << 6) | (tyhi << 9) | (tzlo << 12) | (tzhi << 15);
            for (int tz = tzlo; tz <= tzhi; tz++)
                for (int ty = tylo; ty <= tyhi; ty++)
                    for (int tx = txlo; tx <= txhi; tx++)
                        atomicAdd(&scount[(tz << 6) | (ty << 3) | tx], 1u);
        }
        d_meta[p] = make_int4(ix0, iy0, iz0, w);
    }
    __syncthreads();
    for (int i = t; i < 512; i += 256) {
        unsigned int c = scount[i];
        if (c) atomicAdd(&d_counts[i], c);   // d_counts pre-zeroed by previous run's k_final
    }
}

// ---------------- K3: scans + chunk descriptor emission + sums zero ----------------
__global__ void k_scan() {
    __shared__ unsigned int s[512];
    int t = threadIdx.x;
    unsigned int own = d_counts[t];
    s[t] = own;
    __syncthreads();
    for (int off = 1; off < 512; off <<= 1) {
        unsigned int v = (t >= off) ? s[t - off] : 0u;
        __syncthreads();
        s[t] += v;
        __syncthreads();
    }
    unsigned int segstart = s[t] - own;
    d_segstart[t] = segstart;
    d_cursor[t]   = segstart;
    if (t == 511) d_total = s[511];
    if (t < 3)    d_sums[t] = 0.0;
    __syncthreads();

    unsigned int nch = (own + CHUNK - 1) / CHUNK;
    s[t] = nch;
    __syncthreads();
    for (int off = 1; off < 512; off <<= 1) {
        unsigned int v = (t >= off) ? s[t - off] : 0u;
        __syncthreads();
        s[t] += v;
        __syncthreads();
    }
    unsigned int cb = s[t] - nch;
    if (t == 511) d_nchunks = s[511];

    for (unsigned int j = 0; j * CHUNK < own; j++) {
        unsigned int len = min((unsigned int)CHUNK, own - j * CHUNK);
        d_chunkdesc[cb + j] = make_uint2(segstart + j * CHUNK,
                                         (unsigned int)t | (len << 16));
    }
}

// ---------------- K4: fill entry list, block-aggregated cursors ----------------
__global__ void k_fill() {
    __shared__ unsigned int scount[512];
    __shared__ unsigned int sbase[512];
    int t = threadIdx.x;
    scount[t] = 0u; scount[t + 256] = 0u;
    __syncthreads();

    int p = blockIdx.x * 256 + t;
    int w = (p < P_N) ? d_meta[p].w : -1;
    int txlo = 0, txhi = -1, tylo = 0, tyhi = -1, tzlo = 0, tzhi = -1;
    if (w >= 0) {
        txlo =  w        & 7; txhi = (w >> 3)  & 7;
        tylo = (w >> 6)  & 7; tyhi = (w >> 9)  & 7;
        tzlo = (w >> 12) & 7; tzhi = (w >> 15) & 7;
        for (int tz = tzlo; tz <= tzhi; tz++)
            for (int ty = tylo; ty <= tyhi; ty++)
                for (int tx = txlo; tx <= txhi; tx++)
                    atomicAdd(&scount[(tz << 6) | (ty << 3) | tx], 1u);
    }
    __syncthreads();
    for (int i = t; i < 512; i += 256) {
        unsigned int c = scount[i];
        sbase[i] = c ? atomicAdd(&d_cursor[i], c) : 0u;
    }
    __syncthreads();
    if (w >= 0) {
        for (int tz = tzlo; tz <= tzhi; tz++)
            for (int ty = tylo; ty <= tyhi; ty++)
                for (int tx = txlo; tx <= txhi; tx++) {
                    int tile = (tz << 6) | (ty << 3) | tx;
                    unsigned int posn = atomicAdd(&sbase[tile], 1u);
                    d_entries[posn] = ((unsigned int)tile << 17) | (unsigned int)p;
                }
    }
}

// ---------------- K5: splat — one chunk/CTA, per-x-half compacted dual-entry loops ----------------
__global__ void __launch_bounds__(128) k_splat() {
    __shared__ __align__(16) float sgx[2][NB][16];
    __shared__ __align__(16) float sgy[2][NB][16];
    __shared__ __align__(16) float sgz[2][NB][16];
    __shared__ unsigned int szmask[2][NB];

    if (blockIdx.x >= d_nchunks) return;
    uint2 desc = d_chunkdesc[blockIdx.x];
    unsigned int s   = desc.x;
    int tile         = (int)(desc.y & 0x1FFu);
    unsigned int len = desc.y >> 16;
    unsigned int e_end = s + len;

    int X0 =  (tile       & 7) << 4;
    int Y0 = ((tile >> 3) & 7) << 4;
    int Z0 = ((tile >> 6) & 7) << 4;

    int t    = threadIdx.x;
    int y    = t & 15;        // owned y row
    int zp   = t >> 4;        // owned z rows: 2*zp, 2*zp+1
    int wid  = t >> 5;        // warp id 0..3, covers z in [4w, 4w+4)
    int lane = t & 31;

    ull acc[2][8];            // [zz][x-pair]
    #pragma unroll
    for (int r = 0; r < 2; r++)
        #pragma unroll
        for (int i = 0; i < 8; i++) acc[r][i] = 0ull;

    // stage: float2 granularity; szmask = z bits [0:4) | half0 bit4 | half1 bit5
    // covered tile-local range per axis: l in [-o, (WIN-1)-o]
    auto stage = [&](int buf, unsigned int base, int n) {
        #pragma unroll
        for (int s2 = t; s2 < NB * 8; s2 += 128) {
            int b = s2 >> 3, l2 = s2 & 7;
            if (b < n) {
                unsigned int ent = d_entries[base + (unsigned int)b];
                int pid = (int)(ent & 0x1FFFFu);
                int4 mt = d_meta[pid];
                int ox = X0 - mt.x, oy = Y0 - mt.y, oz = Z0 - mt.z;
                int ix = 2 * l2 + ox, iy = 2 * l2 + oy, iz = 2 * l2 + oz;
                float2 vx = make_float2(0.f, 0.f), vy = vx, vz = vx;
                if ((unsigned)ix < (unsigned)WIN) vx = *(const float2*)&d_gx[pid * 16 + ix];
                if ((unsigned)iy < (unsigned)WIN) vy = *(const float2*)&d_gy[pid * 16 + iy];
                if ((unsigned)iz < (unsigned)WIN) vz = *(const float2*)&d_gz[pid * 16 + iz];
                *(float2*)&sgx[buf][b][2 * l2] = vx;
                *(float2*)&sgy[buf][b][2 * l2] = vy;
                *(float2*)&sgz[buf][b][2 * l2] = vz;
                if (l2 == 0) {
                    int loz = max(0, -oz), hiz = min(15, (WIN - 1) - oz);
                    unsigned int c = 0u;
                    #pragma unroll
                    for (int w2 = 0; w2 < 4; w2++)
                        if (loz <= 4 * w2 + 3 && hiz >= 4 * w2) c |= 1u << w2;
                    int lox = max(0, -ox), hix = min(15, (WIN - 1) - ox);
                    if (lox <= 7) c |= 1u << 4;   // x half 0 covered
                    if (hix >= 8) c |= 1u << 5;   // x half 1 covered
                    szmask[buf][b] = c;
                }
            } else if (l2 == 0) {
                szmask[buf][b] = 0u;
            }
        }
    };

    int nbatch = (int)((len + NB - 1) / NB);
    stage(0, s, (int)min((unsigned int)NB, len));

    for (int i = 0; i < nbatch; i++) {
        __syncthreads();
        int cur = i & 1;
        if (i + 1 < nbatch) {
            unsigned int bnext = s + (unsigned int)(i + 1) * NB;
            stage(cur ^ 1, bnext, (int)min((unsigned int)NB, e_end - bnext));
        }

        unsigned int em = szmask[cur][lane];
        bool zok = (em >> wid) & 1u;
        unsigned int m0 = __ballot_sync(0xFFFFFFFFu, zok && (em & 16u));
        unsigned int m1 = __ballot_sync(0xFFFFFFFFu, zok && (em & 32u));

        // ---- half 0: x pairs 0..3 (sgx slots 0..7) ----
        while (m0) {
            int k1 = __ffs(m0) - 1;
            m0 &= m0 - 1;
            float sec = m0 ? 1.f : 0.f;
            int k2 = m0 ? (__ffs(m0) - 1) : k1;
            m0 &= m0 - 1;

            float  gy1 = sgy[cur][k1][y];
            float2 gza = *(const float2*)&sgz[cur][k1][2 * zp];
            float  gy2 = sgy[cur][k2][y] * sec;
            float2 gzb = *(const float2*)&sgz[cur][k2][2 * zp];
            float a0 = gy1 * gza.x, a1 = gy1 * gza.y;
            float b0 = gy2 * gzb.x, b1 = gy2 * gzb.y;
            ull ca0 = pack2(a0, a0), ca1 = pack2(a1, a1);
            ull cb0 = pack2(b0, b0), cb1 = pack2(b1, b1);

            ulonglong2 pa = *(const ulonglong2*)&sgx[cur][k1][0];
            ulonglong2 pb = *(const ulonglong2*)&sgx[cur][k1][4];
            ulonglong2 qa = *(const ulonglong2*)&sgx[cur][k2][0];
            ulonglong2 qb = *(const ulonglong2*)&sgx[cur][k2][4];

            acc[0][0] = fma2(ca0, pa.x, acc[0][0]); acc[0][1] = fma2(ca0, pa.y, acc[0][1]);
            acc[0][2] = fma2(ca0, pb.x, acc[0][2]); acc[0][3] = fma2(ca0, pb.y, acc[0][3]);
            acc[1][0] = fma2(ca1, pa.x, acc[1][0]); acc[1][1] = fma2(ca1, pa.y, acc[1][1]);
            acc[1][2] = fma2(ca1, pb.x, acc[1][2]); acc[1][3] = fma2(ca1, pb.y, acc[1][3]);
            acc[0][0] = fma2(cb0, qa.x, acc[0][0]); acc[0][1] = fma2(cb0, qa.y, acc[0][1]);
            acc[0][2] = fma2(cb0, qb.x, acc[0][2]); acc[0][3] = fma2(cb0, qb.y, acc[0][3]);
            acc[1][0] = fma2(cb1, qa.x, acc[1][0]); acc[1][1] = fma2(cb1, qa.y, acc[1][1]);
            acc[1][2] = fma2(cb1, qb.x, acc[1][2]); acc[1][3] = fma2(cb1, qb.y, acc[1][3]);
        }

        // ---- half 1: x pairs 4..7 (sgx slots 8..15) ----
        while (m1) {
            int k1 = __ffs(m1) - 1;
            m1 &= m1 - 1;
            float sec = m1 ? 1.f : 0.f;
            int k2 = m1 ? (__ffs(m1) - 1) : k1;
            m1 &= m1 - 1;

            float  gy1 = sgy[cur][k1][y];
            float2 gza = *(const float2*)&sgz[cur][k1][2 * zp];
            float  gy2 = sgy[cur][k2][y] * sec;
            float2 gzb = *(const float2*)&sgz[cur][k2][2 * zp];
            float a0 = gy1 * gza.x, a1 = gy1 * gza.y;
            float b0 = gy2 * gzb.x, b1 = gy2 * gzb.y;
            ull ca0 = pack2(a0, a0), ca1 = pack2(a1, a1);
            ull cb0 = pack2(b0, b0), cb1 = pack2(b1, b1);

            ulonglong2 pc = *(const ulonglong2*)&sgx[cur][k1][8];
            ulonglong2 pd = *(const ulonglong2*)&sgx[cur][k1][12];
            ulonglong2 qc = *(const ulonglong2*)&sgx[cur][k2][8];
            ulonglong2 qd = *(const ulonglong2*)&sgx[cur][k2][12];

            acc[0][4] = fma2(ca0, pc.x, acc[0][4]); acc[0][5] = fma2(ca0, pc.y, acc[0][5]);
            acc[0][6] = fma2(ca0, pd.x, acc[0][6]); acc[0][7] = fma2(ca0, pd.y, acc[0][7]);
            acc[1][4] = fma2(ca1, pc.x, acc[1][4]); acc[1][5] = fma2(ca1, pc.y, acc[1][5]);
            acc[1][6] = fma2(ca1, pd.x, acc[1][6]); acc[1][7] = fma2(ca1, pd.y, acc[1][7]);
            acc[0][4] = fma2(cb0, qc.x, acc[0][4]); acc[0][5] = fma2(cb0, qc.y, acc[0][5]);
            acc[0][6] = fma2(cb0, qd.x, acc[0][6]); acc[0][7] = fma2(cb0, qd.y, acc[0][7]);
            acc[1][4] = fma2(cb1, qc.x, acc[1][4]); acc[1][5] = fma2(cb1, qc.y, acc[1][5]);
            acc[1][6] = fma2(cb1, qd.x, acc[1][6]); acc[1][7] = fma2(cb1, qd.y, acc[1][7]);
        }
    }

    #pragma unroll
    for (int zz = 0; zz < 2; zz++) {
        int rb = ((Z0 + 2 * zp + zz) * 128 + (Y0 + y)) * 128 + X0;
        #pragma unroll
        for (int i2 = 0; i2 < 8; i2++)
            if (acc[zz][i2]) red2(&d_vol[rb + 2 * i2], acc[zz][i2]);
    }
}

// ---------------- K6: fused triple reduction (float inner, double tree) ----------------
__global__ void k_reduce(const float* __restrict__ grid) {
    __shared__ double sh0[256], sh1[256], sh2[256];
    int t = threadIdx.x;
    float s1 = 0.f, s2 = 0.f, s3 = 0.f;
    for (int i = blockIdx.x * 256 + t; i < NVOX; i += gridDim.x * 256) {
        float v = d_vol[i];
        float g = grid[i];
        s1 += v * g;
        s2 += v * v;
        s3 += g * g;
    }
    sh0[t] = (double)s1; sh1[t] = (double)s2; sh2[t] = (double)s3;
    __syncthreads();
    for (int off = 128; off > 0; off >>= 1) {
        if (t < off) {
            sh0[t] += sh0[t + off];
            sh1[t] += sh1[t + off];
            sh2[t] += sh2[t + off];
        }
        __syncthreads();
    }
    if (t == 0) {
        atomicAdd(&d_sums[0], sh0[0]);
        atomicAdd(&d_sums[1], sh1[0]);
        atomicAdd(&d_sums[2], sh2[0]);
    }
}

// ---------------- K7: finish + reset d_counts invariant for the next run ----------------
__global__ void k_final(float* __restrict__ out) {
    int t = threadIdx.x;
    if (t == 0)
        out[0] = (float)(1.0 - d_sums[0] / sqrt(d_sums[1] * d_sums[2]));
    d_counts[t] = 0u;   // 512 threads: restore pre-run invariant
}

extern "C" void kernel_launch(void* const* d_in, const int* in_sizes, int n_in,
                              void* d_out, int out_size) {
    const float* quat   = (const float*)d_in[0];
    const float* offset = (const float*)d_in[1];
    const float* pos    = (const float*)d_in[2];
    const float* amp    = (const float*)d_in[3];
    const float* var    = (const float*)d_in[4];
    const float* grid   = (const float*)d_in[5];
    float* out = (float*)d_out;

    k_precompute<<<PRE_BLOCKS + ZERO_BLOCKS, 256>>>(quat, offset, pos, amp, var);
    k_scan<<<1, 512>>>();
    k_fill<<<(P_N + 255) / 256, 256>>>();
    k_splat<<<MAXC, 128>>>();
    k_reduce<<<512, 256>>>(grid);
    k_final<<<1, 512>>>(out);
}